// round 2
// baseline (speedup 1.0000x reference)
#include <cuda_runtime.h>

// Problem constants
#define Bn   8
#define Sn   1024
#define Dn   512
#define Hn   8
#define DHn  64
#define BHn  (Bn * Hn)      // 64
#define Mn   (Bn * Sn)      // 8192
#define SCALE 0.044194173824159216f   // 1/sqrt(512)

// Scratch (device globals — no allocation allowed). 336 MB total.
static __device__ float g_q[Mn * Dn];
static __device__ float g_k[Mn * Dn];
static __device__ float g_v[Mn * Dn];
static __device__ float g_p[Mn * Dn];
static __device__ float g_ctx[Mn * Dn];
static __device__ float g_sc[(size_t)BHn * Sn * Sn];   // shifted pos -> combined -> softmax

// ---------------------------------------------------------------------------
// Projection GEMM: C[8192,512] = X[8192,512] @ W[512,512] (+ bias)
// 64x64 block tile, BK=16, 256 threads, 4x4 per-thread micro-tile.
// ---------------------------------------------------------------------------
__global__ void proj_gemm(const float* __restrict__ X, const float* __restrict__ W,
                          const float* __restrict__ bias, int dst_sel) {
    float* C = (dst_sel == 0) ? g_q : (dst_sel == 1) ? g_k : (dst_sel == 2) ? g_v : g_p;
    __shared__ float As[16][65];
    __shared__ float Bs[16][68];
    const int tid = threadIdx.x;
    const int tx = tid & 15, ty = tid >> 4;
    const int mb = blockIdx.y * 64, nb = blockIdx.x * 64;
    const int lr = tid >> 2, lc = (tid & 3) << 2;   // A: 64 rows x 16 cols
    const int br = tid >> 4, bc = (tid & 15) << 2;  // B: 16 rows x 64 cols
    float acc[4][4] = {};
    for (int k0 = 0; k0 < Dn; k0 += 16) {
        float4 a4 = *(const float4*)(X + (size_t)(mb + lr) * Dn + k0 + lc);
        As[lc + 0][lr] = a4.x; As[lc + 1][lr] = a4.y;
        As[lc + 2][lr] = a4.z; As[lc + 3][lr] = a4.w;
        float4 b4 = *(const float4*)(W + (size_t)(k0 + br) * Dn + nb + bc);
        *(float4*)&Bs[br][bc] = b4;
        __syncthreads();
        #pragma unroll
        for (int k = 0; k < 16; k++) {
            float a[4], b[4];
            #pragma unroll
            for (int i = 0; i < 4; i++) a[i] = As[k][ty * 4 + i];
            #pragma unroll
            for (int j = 0; j < 4; j++) b[j] = Bs[k][tx * 4 + j];
            #pragma unroll
            for (int i = 0; i < 4; i++)
                #pragma unroll
                for (int j = 0; j < 4; j++)
                    acc[i][j] = fmaf(a[i], b[j], acc[i][j]);
        }
        __syncthreads();
    }
    #pragma unroll
    for (int i = 0; i < 4; i++) {
        const int m = mb + ty * 4 + i;
        #pragma unroll
        for (int j = 0; j < 4; j++) {
            const int n = nb + tx * 4 + j;
            float v = acc[i][j];
            if (bias) v += bias[n];
            C[(size_t)m * Dn + n] = v;
        }
    }
}

// ---------------------------------------------------------------------------
// Output GEMM: out[8192,512] = g_ctx @ Wo + bo
// ---------------------------------------------------------------------------
__global__ void out_gemm(const float* __restrict__ W, const float* __restrict__ bias,
                         float* __restrict__ C) {
    __shared__ float As[16][65];
    __shared__ float Bs[16][68];
    const int tid = threadIdx.x;
    const int tx = tid & 15, ty = tid >> 4;
    const int mb = blockIdx.y * 64, nb = blockIdx.x * 64;
    const int lr = tid >> 2, lc = (tid & 3) << 2;
    const int br = tid >> 4, bc = (tid & 15) << 2;
    float acc[4][4] = {};
    for (int k0 = 0; k0 < Dn; k0 += 16) {
        float4 a4 = *(const float4*)(g_ctx + (size_t)(mb + lr) * Dn + k0 + lc);
        As[lc + 0][lr] = a4.x; As[lc + 1][lr] = a4.y;
        As[lc + 2][lr] = a4.z; As[lc + 3][lr] = a4.w;
        float4 b4 = *(const float4*)(W + (size_t)(k0 + br) * Dn + nb + bc);
        *(float4*)&Bs[br][bc] = b4;
        __syncthreads();
        #pragma unroll
        for (int k = 0; k < 16; k++) {
            float a[4], b[4];
            #pragma unroll
            for (int i = 0; i < 4; i++) a[i] = As[k][ty * 4 + i];
            #pragma unroll
            for (int j = 0; j < 4; j++) b[j] = Bs[k][tx * 4 + j];
            #pragma unroll
            for (int i = 0; i < 4; i++)
                #pragma unroll
                for (int j = 0; j < 4; j++)
                    acc[i][j] = fmaf(a[i], b[j], acc[i][j]);
        }
        __syncthreads();
    }
    #pragma unroll
    for (int i = 0; i < 4; i++) {
        const int m = mb + ty * 4 + i;
        #pragma unroll
        for (int j = 0; j < 4; j++) {
            const int n = nb + tx * 4 + j;
            C[(size_t)m * Dn + n] = acc[i][j] + bias[n];
        }
    }
}

// ---------------------------------------------------------------------------
// Score GEMMs, per (b,h), S x S over K=Dh=64.
//
// Pass 0 (SHIFT=0, hb=v_bias): compute P[i,c] = (q_i+vb).p_c and SCATTER into
// g_sc in shifted position (each P element maps to exactly one R element):
//   c >= S-1-i -> R[i,   c-S+1+i]
//   c <  S-1-i -> R[i-1, c+i+1]     (dropped when i == 0)
// R[i, i+1] is never written (it is identically 0 in the reference).
//
// Pass 1 (SHIFT=1, hb=u_bias): compute content score and RMW in-place:
//   g_sc[i,j] = (content[i,j] + (j==i+1 ? 0 : g_sc[i,j])) * SCALE
// ---------------------------------------------------------------------------
template <int SHIFT>
__global__ void score_gemm(const float* __restrict__ hb) {
    const int bh = blockIdx.z;
    const int b = bh >> 3, h = bh & 7;
    const float* A  = g_q + (size_t)b * Sn * Dn + h * DHn;
    const float* Bm = (SHIFT ? g_k : g_p) + (size_t)b * Sn * Dn + h * DHn;
    __shared__ float As[16][65];
    __shared__ float Bs[16][65];
    const int tid = threadIdx.x;
    const int tx = tid & 15, ty = tid >> 4;
    const int ib = blockIdx.y * 64, jb = blockIdx.x * 64;
    const int lr = tid >> 2, lc = (tid & 3) << 2;
    float acc[4][4] = {};
    for (int k0 = 0; k0 < DHn; k0 += 16) {
        float4 a4 = *(const float4*)(A + (size_t)(ib + lr) * Dn + k0 + lc);
        As[lc + 0][lr] = a4.x + hb[h * DHn + k0 + lc + 0];
        As[lc + 1][lr] = a4.y + hb[h * DHn + k0 + lc + 1];
        As[lc + 2][lr] = a4.z + hb[h * DHn + k0 + lc + 2];
        As[lc + 3][lr] = a4.w + hb[h * DHn + k0 + lc + 3];
        float4 b4 = *(const float4*)(Bm + (size_t)(jb + lr) * Dn + k0 + lc);
        Bs[lc + 0][lr] = b4.x; Bs[lc + 1][lr] = b4.y;
        Bs[lc + 2][lr] = b4.z; Bs[lc + 3][lr] = b4.w;
        __syncthreads();
        #pragma unroll
        for (int k = 0; k < 16; k++) {
            float a[4], b[4];
            #pragma unroll
            for (int i = 0; i < 4; i++) a[i] = As[k][ty * 4 + i];
            #pragma unroll
            for (int j = 0; j < 4; j++) b[j] = Bs[k][tx * 4 + j];
            #pragma unroll
            for (int i = 0; i < 4; i++)
                #pragma unroll
                for (int j = 0; j < 4; j++)
                    acc[i][j] = fmaf(a[i], b[j], acc[i][j]);
        }
        __syncthreads();
    }
    const size_t base = (size_t)bh * Sn * Sn;
    #pragma unroll
    for (int ii = 0; ii < 4; ii++) {
        const int i = ib + ty * 4 + ii;
        #pragma unroll
        for (int jj = 0; jj < 4; jj++) {
            const int j = jb + tx * 4 + jj;   // column of P (pass0) or of score (pass1)
            if (SHIFT) {
                float ps = (j == i + 1) ? 0.0f : g_sc[base + (size_t)i * Sn + j];
                g_sc[base + (size_t)i * Sn + j] = (acc[ii][jj] + ps) * SCALE;
            } else {
                // scatter P[i, j] into shifted position
                if (j >= Sn - 1 - i) {
                    g_sc[base + (size_t)i * Sn + (j - Sn + 1 + i)] = acc[ii][jj];
                } else if (i > 0) {
                    g_sc[base + (size_t)(i - 1) * Sn + (j + i + 1)] = acc[ii][jj];
                }
            }
        }
    }
}

// ---------------------------------------------------------------------------
// Row softmax over g_sc, in-place. One block per row (1024 elems, 256 thr).
// ---------------------------------------------------------------------------
__global__ void softmax_rows() {
    float* r = g_sc + (size_t)blockIdx.x * Sn;
    const int t = threadIdx.x;
    float4 v = reinterpret_cast<float4*>(r)[t];
    float m = fmaxf(fmaxf(v.x, v.y), fmaxf(v.z, v.w));
    #pragma unroll
    for (int o = 16; o; o >>= 1) m = fmaxf(m, __shfl_xor_sync(0xffffffffu, m, o));
    __shared__ float red[8];
    if ((t & 31) == 0) red[t >> 5] = m;
    __syncthreads();
    float bmax = red[0];
    #pragma unroll
    for (int i = 1; i < 8; i++) bmax = fmaxf(bmax, red[i]);
    __syncthreads();
    v.x = __expf(v.x - bmax); v.y = __expf(v.y - bmax);
    v.z = __expf(v.z - bmax); v.w = __expf(v.w - bmax);
    float s = v.x + v.y + v.z + v.w;
    #pragma unroll
    for (int o = 16; o; o >>= 1) s += __shfl_xor_sync(0xffffffffu, s, o);
    if ((t & 31) == 0) red[t >> 5] = s;
    __syncthreads();
    float tot = 0.0f;
    #pragma unroll
    for (int i = 0; i < 8; i++) tot += red[i];
    const float inv = 1.0f / tot;
    v.x *= inv; v.y *= inv; v.z *= inv; v.w *= inv;
    reinterpret_cast<float4*>(r)[t] = v;
}

// ---------------------------------------------------------------------------
// Context GEMM, per (b,h): ctx[i, h*64+n] = sum_j atten[i,j] * v[j, h*64+n]
// M=1024, N=64, K=1024.
// ---------------------------------------------------------------------------
__global__ void av_gemm() {
    const int bh = blockIdx.z;
    const int b = bh >> 3, h = bh & 7;
    const float* A  = g_sc + (size_t)bh * Sn * Sn;
    const float* Bm = g_v + (size_t)b * Sn * Dn + h * DHn;
    __shared__ float As[16][65];
    __shared__ float Bs[16][68];
    const int tid = threadIdx.x;
    const int tx = tid & 15, ty = tid >> 4;
    const int ib = blockIdx.y * 64;
    const int lr = tid >> 2, lc = (tid & 3) << 2;
    const int br = tid >> 4, bc = (tid & 15) << 2;
    float acc[4][4] = {};
    for (int k0 = 0; k0 < Sn; k0 += 16) {
        float4 a4 = *(const float4*)(A + (size_t)(ib + lr) * Sn + k0 + lc);
        As[lc + 0][lr] = a4.x; As[lc + 1][lr] = a4.y;
        As[lc + 2][lr] = a4.z; As[lc + 3][lr] = a4.w;
        float4 b4 = *(const float4*)(Bm + (size_t)(k0 + br) * Dn + bc);
        *(float4*)&Bs[br][bc] = b4;
        __syncthreads();
        #pragma unroll
        for (int k = 0; k < 16; k++) {
            float a[4], b[4];
            #pragma unroll
            for (int i = 0; i < 4; i++) a[i] = As[k][ty * 4 + i];
            #pragma unroll
            for (int j = 0; j < 4; j++) b[j] = Bs[k][tx * 4 + j];
            #pragma unroll
            for (int i = 0; i < 4; i++)
                #pragma unroll
                for (int j = 0; j < 4; j++)
                    acc[i][j] = fmaf(a[i], b[j], acc[i][j]);
        }
        __syncthreads();
    }
    #pragma unroll
    for (int ii = 0; ii < 4; ii++) {
        const int i = ib + ty * 4 + ii;
        #pragma unroll
        for (int jj = 0; jj < 4; jj++) {
            g_ctx[(size_t)(b * Sn + i) * Dn + h * DHn + tx * 4 + jj] = acc[ii][jj];
        }
    }
}

// ---------------------------------------------------------------------------
extern "C" void kernel_launch(void* const* d_in, const int* in_sizes, int n_in,
                              void* d_out, int out_size) {
    (void)in_sizes; (void)n_in; (void)out_size;
    const float* query = (const float*)d_in[0];
    const float* key   = (const float*)d_in[1];
    const float* value = (const float*)d_in[2];
    const float* pemb  = (const float*)d_in[3];
    const float* Wq    = (const float*)d_in[4];
    const float* bq    = (const float*)d_in[5];
    const float* Wk    = (const float*)d_in[6];
    const float* bk    = (const float*)d_in[7];
    const float* Wv    = (const float*)d_in[8];
    const float* bv    = (const float*)d_in[9];
    const float* Wp    = (const float*)d_in[10];
    const float* u_bias = (const float*)d_in[11];
    const float* v_bias = (const float*)d_in[12];
    const float* Wo    = (const float*)d_in[13];
    const float* bo    = (const float*)d_in[14];
    float* out = (float*)d_out;

    dim3 gproj(Dn / 64, Mn / 64);     // (8, 128)
    proj_gemm<<<gproj, 256>>>(query, Wq, bq, 0);
    proj_gemm<<<gproj, 256>>>(key,   Wk, bk, 1);
    proj_gemm<<<gproj, 256>>>(value, Wv, bv, 2);
    proj_gemm<<<gproj, 256>>>(pemb,  Wp, nullptr, 3);

    dim3 gsc(Sn / 64, Sn / 64, BHn);  // (16, 16, 64)
    score_gemm<0><<<gsc, 256>>>(v_bias);   // pos scores scattered (shifted) -> g_sc
    score_gemm<1><<<gsc, 256>>>(u_bias);   // content + pos, scaled -> g_sc

    softmax_rows<<<BHn * Sn, 256>>>();

    dim3 gav(1, Sn / 64, BHn);        // (1, 16, 64)
    av_gemm<<<gav, 256>>>();

    out_gemm<<<gproj, 256>>>(Wo, bo, out);
}